// round 5
// baseline (speedup 1.0000x reference)
#include <cuda_runtime.h>
#include <cstdint>

#define S_LEN 2048
#define BATCH 256
#define INSZ  32
#define HID   8
#define G4    32          // 4*HID gates
#define NBLK  80
#define OUTSZ 128
#define NROWS (S_LEN*BATCH)   // 524288

// Scratch (__device__ globals; no runtime allocation)
// g_xg layout: [row][unit*4 + gate_type]  (i,f,g,o interleaved per unit)
__device__ float g_xg[(size_t)NROWS * G4];   // 64 MB
__device__ float g_ys[(size_t)NROWS * HID];  // 16 MB: LSTM hidden outputs

__device__ __forceinline__ float tanha(float x) {
    float r; asm("tanh.approx.f32 %0, %1;" : "=f"(r) : "f"(x)); return r;
}
__device__ __forceinline__ float leaky(float v) { return fmaxf(v, 0.01f * v); }

// ---------------------------------------------------------------------------
// K1: xg[row][u*4+t] = s(t) * ( x[row].w_ih[t*8+u] + b_ih + b_hh )
//     s = 0.5 for sigmoid gates (i,f,o), 1.0 for tanh gate.
// ---------------------------------------------------------------------------
__global__ void __launch_bounds__(256) k1_xw(
    const float* __restrict__ x, const float* __restrict__ w_ih,
    const float* __restrict__ b_ih, const float* __restrict__ b_hh)
{
    __shared__ float4 sx[256 * 8];     // 32 KB: 256 rows of x
    __shared__ float  swp[32 * 33];    // padded weights

    const int tid  = threadIdx.x;
    const int lane = tid & 31;
    const int wid  = tid >> 5;

#pragma unroll
    for (int k = 0; k < 4; k++) {
        const int idx = tid + k * 256;          // 1024 floats
        const int g = idx >> 5, j = idx & 31;
        const float s = ((g >> 3) == 2) ? 1.f : 0.5f;
        swp[g * 33 + j] = w_ih[idx] * s;
    }

    const size_t rowbase = (size_t)blockIdx.x * 256;
    const float4* xg4 = (const float4*)x + rowbase * 8;
#pragma unroll
    for (int i = 0; i < 8; i++) sx[tid + i * 256] = xg4[tid + i * 256];

    __syncthreads();

    float w[32];
#pragma unroll
    for (int j = 0; j < 32; j++) w[j] = swp[lane * 33 + j];
    const float s2 = ((lane >> 3) == 2) ? 1.f : 0.5f;
    const float bias = (b_ih[lane] + b_hh[lane]) * s2;

    // unit-major output column: u*4 + type
    const int ocol = (lane & 7) * 4 + (lane >> 3);

    float* op = g_xg + (rowbase + wid * 32) * 32 + ocol;
    const float4* xr0 = &sx[wid * 32 * 8];

#pragma unroll 4
    for (int r = 0; r < 32; r++) {
        const float4* xr = xr0 + r * 8;
        float a0 = bias, a1 = 0.f, a2 = 0.f, a3 = 0.f;
#pragma unroll
        for (int j4 = 0; j4 < 8; j4++) {
            const float4 v = xr[j4];            // broadcast LDS.128
            a0 = fmaf(w[j4 * 4 + 0], v.x, a0);
            a1 = fmaf(w[j4 * 4 + 1], v.y, a1);
            a2 = fmaf(w[j4 * 4 + 2], v.z, a2);
            a3 = fmaf(w[j4 * 4 + 3], v.w, a3);
        }
        op[(size_t)r * 32] = (a0 + a1) + (a2 + a3);   // coalesced STG.32
    }
}

// ---------------------------------------------------------------------------
// K2: sequential LSTM. 8 batch chains per warp: 4 via lane groups
//     (lane = bsub*8+unit) x 2 via register-level ILP (chains A and B).
//     Each lane computes all 4 gates of its unit (no gather shuffle);
//     h broadcast via width-8 shfl. The two chains interleave in one basic
//     block so SHFL/MUFU latency of one is hidden by the other's FMAs.
// ---------------------------------------------------------------------------
#define PF 4
__global__ void __launch_bounds__(32, 1) k2_lstm(
    const float* __restrict__ h0, const float* __restrict__ c0,
    const float* __restrict__ w_hh, float* __restrict__ out)
{
    const int lane = threadIdx.x;
    const int blk  = blockIdx.x;           // 32 blocks, 8 batch elems each
    const int unit = lane & 7;

    // weights shared by both chains (same unit)
    float w[4][8];
#pragma unroll
    for (int t = 0; t < 4; t++) {
        const float s = (t == 2) ? 1.f : 0.5f;
#pragma unroll
        for (int j = 0; j < 8; j++) w[t][j] = w_hh[(t * 8 + unit) * 8 + j] * s;
    }

    // chain A: batch blk*8 + bsub;  chain B: batch blk*8 + 4 + bsub
    float hA = h0[blk * 64 + lane],      cA = c0[blk * 64 + lane];
    float hB = h0[blk * 64 + 32 + lane], cB = c0[blk * 64 + 32 + lane];

    // xg float4 index: t*2048 + blk*64 + (bsub*8+unit) [+32 for B]
    const float4* xpA = (const float4*)g_xg + (size_t)blk * 64 + lane;
    const float4* xpB = xpA + 32;
    float* ypA = g_ys + blk * 64 + lane;           // + t*2048
    float* ypB = ypA + 32;

    float4 bufA[PF], bufB[PF];
#pragma unroll
    for (int k = 0; k < PF; k++) {
        bufA[k] = __ldg(xpA + (size_t)k * 2048);
        bufB[k] = __ldg(xpB + (size_t)k * 2048);
    }

#define K2_CH(H, C, XG)                                                       \
    {                                                                         \
        float hs[8];                                                          \
        _Pragma("unroll")                                                     \
        for (int j = 0; j < 8; j++)                                           \
            hs[j] = __shfl_sync(0xffffffffu, H, j, 8);                        \
        float i0 = XG.x, i1 = 0.f, f0 = XG.y, f1 = 0.f;                       \
        float gg0 = XG.z, gg1 = 0.f, o0 = XG.w, o1 = 0.f;                     \
        _Pragma("unroll")                                                     \
        for (int j = 0; j < 4; j++) {                                         \
            f0  = fmaf(w[1][j], hs[j], f0);                                   \
            f1  = fmaf(w[1][j + 4], hs[j + 4], f1);                           \
            gg0 = fmaf(w[2][j], hs[j], gg0);                                  \
            gg1 = fmaf(w[2][j + 4], hs[j + 4], gg1);                          \
            i0  = fmaf(w[0][j], hs[j], i0);                                   \
            i1  = fmaf(w[0][j + 4], hs[j + 4], i1);                           \
            o0  = fmaf(w[3][j], hs[j], o0);                                   \
            o1  = fmaf(w[3][j + 4], hs[j + 4], o1);                           \
        }                                                                     \
        const float vf = tanha(f0 + f1);                                      \
        const float vg = tanha(gg0 + gg1);                                    \
        const float vi = tanha(i0 + i1);                                      \
        const float vo = tanha(o0 + o1);                                      \
        const float fg = fmaf(vf, 0.5f, 0.5f);                                \
        const float ig = fmaf(vi, 0.5f, 0.5f);                                \
        const float og = fmaf(vo, 0.5f, 0.5f);                                \
        C = fmaf(fg, C, ig * vg);                                             \
        H = og * tanha(C);                                                    \
    }

#define K2_STEP2(T2, DO_PF)                                                   \
    {                                                                         \
        const int k_ = (T2) & (PF - 1);                                       \
        const float4 xa = bufA[k_];                                           \
        const float4 xb = bufB[k_];                                           \
        K2_CH(hA, cA, xa)                                                     \
        K2_CH(hB, cB, xb)                                                     \
        ypA[(size_t)(T2) * 2048] = hA;                                        \
        ypB[(size_t)(T2) * 2048] = hB;                                        \
        if (DO_PF) {                                                          \
            bufA[k_] = __ldg(xpA + (size_t)((T2) + PF) * 2048);               \
            bufB[k_] = __ldg(xpB + (size_t)((T2) + PF) * 2048);               \
        }                                                                     \
    }

    int t = 0;
#pragma unroll 1
    for (; t < S_LEN - PF; t += PF) {
#pragma unroll
        for (int k = 0; k < PF; k++) K2_STEP2(t + k, true)
    }
#pragma unroll
    for (int k = 0; k < PF; k++) K2_STEP2(t + k, false)

    const size_t fb = (size_t)NROWS * OUTSZ;
    out[fb + blk * 64 + lane]      = hA;                          // h_f
    out[fb + blk * 64 + 32 + lane] = hB;
    out[fb + BATCH * HID + blk * 64 + lane]      = cA;            // c_f
    out[fb + BATCH * HID + blk * 64 + 32 + lane] = cB;
}

// ---------------------------------------------------------------------------
// K3: residual MLP head. Lane per (t,b) row through 80-block chain,
//     warp-transpose via shfl for the 128-wide expansion -> STG.128.
// ---------------------------------------------------------------------------
__global__ void __launch_bounds__(256) k3_res(
    const float* __restrict__ w_in,  const float* __restrict__ b_in,
    const float* __restrict__ rb_w1, const float* __restrict__ rb_b1,
    const float* __restrict__ rb_w2, const float* __restrict__ rb_b2,
    const float* __restrict__ w_bn,  const float* __restrict__ b_bn,
    const float* __restrict__ w_out, const float* __restrict__ b_out,
    float* __restrict__ out)
{
    __shared__ float4 s_w1[NBLK], s_w2[NBLK], s_b2[NBLK];
    __shared__ float  s_b1[NBLK];
    for (int i = threadIdx.x; i < NBLK; i += blockDim.x) {
        s_w1[i] = ((const float4*)rb_w1)[i];
        s_w2[i] = ((const float4*)rb_w2)[i];
        s_b2[i] = ((const float4*)rb_b2)[i];
        s_b1[i] = rb_b1[i];
    }
    __syncthreads();

    const int lane  = threadIdx.x & 31;
    const int warpg = (blockIdx.x * blockDim.x + threadIdx.x) >> 5;
    const int base  = warpg * 32;           // 16384 warps cover 524288 rows
    const int e     = base + lane;

    const float4 ha = *(const float4*)(g_ys + (size_t)e * 8);
    const float4 hb = *(const float4*)(g_ys + (size_t)e * 8 + 4);
    const float hv[8] = {ha.x, ha.y, ha.z, ha.w, hb.x, hb.y, hb.z, hb.w};

    float y[4];
#pragma unroll
    for (int i = 0; i < 4; i++) {
        float a = b_in[i];
#pragma unroll
        for (int j = 0; j < 8; j++) a = fmaf(w_in[i * 8 + j], hv[j], a);
        y[i] = leaky(a);
    }

#pragma unroll 2
    for (int blk = 0; blk < NBLK; blk++) {
        const float4 w1 = s_w1[blk];
        const float4 w2 = s_w2[blk];
        const float4 b2 = s_b2[blk];
        float z = s_b1[blk];
        z = fmaf(w1.x, y[0], z);
        z = fmaf(w1.y, y[1], z);
        z = fmaf(w1.z, y[2], z);
        z = fmaf(w1.w, y[3], z);
        z = leaky(z);
        y[0] = leaky(fmaf(w2.x, z, y[0]) + b2.x);
        y[1] = leaky(fmaf(w2.y, z, y[1]) + b2.y);
        y[2] = leaky(fmaf(w2.z, z, y[2]) + b2.z);
        y[3] = leaky(fmaf(w2.w, z, y[3]) + b2.w);
    }

    float yb = b_bn[0];
    yb = fmaf(w_bn[0], y[0], yb);
    yb = fmaf(w_bn[1], y[1], yb);
    yb = fmaf(w_bn[2], y[2], yb);
    yb = fmaf(w_bn[3], y[3], yb);
    yb = leaky(yb);

    // sigmoid(a*w+b) = 0.5 + 0.5*tanh(0.5*(a*w+b)) -> pre-halved w,b
    float4 wo = *(const float4*)(w_out + lane * 4);
    float4 bo = *(const float4*)(b_out + lane * 4);
    wo.x *= 0.5f; wo.y *= 0.5f; wo.z *= 0.5f; wo.w *= 0.5f;
    bo.x *= 0.5f; bo.y *= 0.5f; bo.z *= 0.5f; bo.w *= 0.5f;
    float* op = out + (size_t)base * OUTSZ + lane * 4;

#pragma unroll
    for (int cidx = 0; cidx < 32; cidx++) {
        const float ybc = __shfl_sync(0xffffffffu, yb, cidx);
        float4 o;
        o.x = fmaf(tanha(fmaf(ybc, wo.x, bo.x)), 0.5f, 0.5f);
        o.y = fmaf(tanha(fmaf(ybc, wo.y, bo.y)), 0.5f, 0.5f);
        o.z = fmaf(tanha(fmaf(ybc, wo.z, bo.z)), 0.5f, 0.5f);
        o.w = fmaf(tanha(fmaf(ybc, wo.w, bo.w)), 0.5f, 0.5f);
        *(float4*)(op + (size_t)cidx * OUTSZ) = o;
    }
}

// ---------------------------------------------------------------------------
extern "C" void kernel_launch(void* const* d_in, const int* in_sizes, int n_in,
                              void* d_out, int out_size)
{
    const float* x     = (const float*)d_in[0];
    const float* h     = (const float*)d_in[1];
    const float* c     = (const float*)d_in[2];
    const float* w_ih  = (const float*)d_in[3];
    const float* w_hh  = (const float*)d_in[4];
    const float* b_ih  = (const float*)d_in[5];
    const float* b_hh  = (const float*)d_in[6];
    const float* w_in  = (const float*)d_in[7];
    const float* b_in  = (const float*)d_in[8];
    const float* rb_w1 = (const float*)d_in[9];
    const float* rb_b1 = (const float*)d_in[10];
    const float* rb_w2 = (const float*)d_in[11];
    const float* rb_b2 = (const float*)d_in[12];
    const float* w_bn  = (const float*)d_in[13];
    const float* b_bn  = (const float*)d_in[14];
    const float* w_out = (const float*)d_in[15];
    const float* b_out = (const float*)d_in[16];
    float* out = (float*)d_out;

    k1_xw<<<2048, 256>>>(x, w_ih, b_ih, b_hh);
    k2_lstm<<<BATCH / 8, 32>>>(h, c, w_hh, out);
    k3_res<<<2048, 256>>>(w_in, b_in, rb_w1, rb_b1, rb_w2, rb_b2,
                          w_bn, b_bn, w_out, b_out, out);
}

// round 6
// speedup vs baseline: 1.0035x; 1.0035x over previous
#include <cuda_runtime.h>
#include <cstdint>

#define S_LEN 2048
#define BATCH 256
#define INSZ  32
#define HID   8
#define G4    32          // 4*HID gates
#define NBLK  80
#define OUTSZ 128
#define NROWS (S_LEN*BATCH)   // 524288

// Scratch (__device__ globals; no runtime allocation)
// g_xg layout: [row][unit*4 + gate_type]  (i,f,g,o interleaved per unit)
__device__ float g_xg[(size_t)NROWS * G4];   // 64 MB
__device__ float g_ys[(size_t)NROWS * HID];  // 16 MB: LSTM hidden outputs

__device__ __forceinline__ float tanha(float x) {
    float r; asm("tanh.approx.f32 %0, %1;" : "=f"(r) : "f"(x)); return r;
}
__device__ __forceinline__ float leaky(float v) { return fmaxf(v, 0.01f * v); }

// ---------------------------------------------------------------------------
// K1: xg[row][u*4+t] = s(t) * ( x[row].w_ih[t*8+u] + b_ih + b_hh )
//     s = 0.5 for sigmoid gates (i,f,o), 1.0 for tanh gate.
// ---------------------------------------------------------------------------
__global__ void __launch_bounds__(256) k1_xw(
    const float* __restrict__ x, const float* __restrict__ w_ih,
    const float* __restrict__ b_ih, const float* __restrict__ b_hh)
{
    __shared__ float4 sx[256 * 8];     // 32 KB: 256 rows of x
    __shared__ float  swp[32 * 33];    // padded weights

    const int tid  = threadIdx.x;
    const int lane = tid & 31;
    const int wid  = tid >> 5;

#pragma unroll
    for (int k = 0; k < 4; k++) {
        const int idx = tid + k * 256;          // 1024 floats
        const int g = idx >> 5, j = idx & 31;
        const float s = ((g >> 3) == 2) ? 1.f : 0.5f;
        swp[g * 33 + j] = w_ih[idx] * s;
    }

    const size_t rowbase = (size_t)blockIdx.x * 256;
    const float4* xg4 = (const float4*)x + rowbase * 8;
#pragma unroll
    for (int i = 0; i < 8; i++) sx[tid + i * 256] = xg4[tid + i * 256];

    __syncthreads();

    float w[32];
#pragma unroll
    for (int j = 0; j < 32; j++) w[j] = swp[lane * 33 + j];
    const float s2 = ((lane >> 3) == 2) ? 1.f : 0.5f;
    const float bias = (b_ih[lane] + b_hh[lane]) * s2;

    // unit-major output column: u*4 + type
    const int ocol = (lane & 7) * 4 + (lane >> 3);

    float* op = g_xg + (rowbase + wid * 32) * 32 + ocol;
    const float4* xr0 = &sx[wid * 32 * 8];

#pragma unroll 4
    for (int r = 0; r < 32; r++) {
        const float4* xr = xr0 + r * 8;
        float a0 = bias, a1 = 0.f, a2 = 0.f, a3 = 0.f;
#pragma unroll
        for (int j4 = 0; j4 < 8; j4++) {
            const float4 v = xr[j4];            // broadcast LDS.128
            a0 = fmaf(w[j4 * 4 + 0], v.x, a0);
            a1 = fmaf(w[j4 * 4 + 1], v.y, a1);
            a2 = fmaf(w[j4 * 4 + 2], v.z, a2);
            a3 = fmaf(w[j4 * 4 + 3], v.w, a3);
        }
        op[(size_t)r * 32] = (a0 + a1) + (a2 + a3);   // coalesced STG.32
    }
}

// ---------------------------------------------------------------------------
// K2: sequential LSTM. 8 batch chains per warp (4 lane-groups x 2 register
//     chains) with MANUAL source-level interleaving: all shuffles for both
//     chains first (convergent ops keep source order), then interleaved
//     dots, then all MUFUs, then both updates. This hides each chain's
//     SHFL/MUFU latency under the other chain's work.
// ---------------------------------------------------------------------------
#define PF 4
__global__ void __launch_bounds__(32, 1) k2_lstm(
    const float* __restrict__ h0, const float* __restrict__ c0,
    const float* __restrict__ w_hh, float* __restrict__ out)
{
    const int lane = threadIdx.x;
    const int blk  = blockIdx.x;           // 32 blocks, 8 batch elems each
    const int unit = lane & 7;

    // weights shared by both chains (same unit)
    float w[4][8];
#pragma unroll
    for (int t = 0; t < 4; t++) {
        const float s = (t == 2) ? 1.f : 0.5f;
#pragma unroll
        for (int j = 0; j < 8; j++) w[t][j] = w_hh[(t * 8 + unit) * 8 + j] * s;
    }

    // chain A: batch blk*8 + bsub;  chain B: batch blk*8 + 4 + bsub
    float hA = h0[blk * 64 + lane],      cA = c0[blk * 64 + lane];
    float hB = h0[blk * 64 + 32 + lane], cB = c0[blk * 64 + 32 + lane];

    const float4* xpA = (const float4*)g_xg + (size_t)blk * 64 + lane;
    const float4* xpB = xpA + 32;
    float* ypA = g_ys + blk * 64 + lane;           // + t*2048
    float* ypB = ypA + 32;

    float4 bufA[PF], bufB[PF];
#pragma unroll
    for (int k = 0; k < PF; k++) {
        bufA[k] = __ldg(xpA + (size_t)k * 2048);
        bufB[k] = __ldg(xpB + (size_t)k * 2048);
    }

#define K2_STEP2(T2, DO_PF)                                                   \
    {                                                                         \
        const int k_ = (T2) & (PF - 1);                                       \
        const float4 xa = bufA[k_];                                           \
        const float4 xb = bufB[k_];                                           \
        /* phase 1: ALL shuffles, both chains, back to back */                \
        float hsA[8], hsB[8];                                                 \
        _Pragma("unroll")                                                     \
        for (int j = 0; j < 8; j++)                                           \
            hsA[j] = __shfl_sync(0xffffffffu, hA, j, 8);                      \
        _Pragma("unroll")                                                     \
        for (int j = 0; j < 8; j++)                                           \
            hsB[j] = __shfl_sync(0xffffffffu, hB, j, 8);                      \
        /* phase 2: both dot products, interleaved */                         \
        float iA0 = xa.x, fA0 = xa.y, gA0 = xa.z, oA0 = xa.w;                 \
        float iA1 = 0.f, fA1 = 0.f, gA1 = 0.f, oA1 = 0.f;                     \
        float iB0 = xb.x, fB0 = xb.y, gB0 = xb.z, oB0 = xb.w;                 \
        float iB1 = 0.f, fB1 = 0.f, gB1 = 0.f, oB1 = 0.f;                     \
        _Pragma("unroll")                                                     \
        for (int j = 0; j < 4; j++) {                                         \
            fA0 = fmaf(w[1][j],     hsA[j],     fA0);                         \
            fB0 = fmaf(w[1][j],     hsB[j],     fB0);                         \
            fA1 = fmaf(w[1][j + 4], hsA[j + 4], fA1);                         \
            fB1 = fmaf(w[1][j + 4], hsB[j + 4], fB1);                         \
            gA0 = fmaf(w[2][j],     hsA[j],     gA0);                         \
            gB0 = fmaf(w[2][j],     hsB[j],     gB0);                         \
            gA1 = fmaf(w[2][j + 4], hsA[j + 4], gA1);                         \
            gB1 = fmaf(w[2][j + 4], hsB[j + 4], gB1);                         \
            iA0 = fmaf(w[0][j],     hsA[j],     iA0);                         \
            iB0 = fmaf(w[0][j],     hsB[j],     iB0);                         \
            iA1 = fmaf(w[0][j + 4], hsA[j + 4], iA1);                         \
            iB1 = fmaf(w[0][j + 4], hsB[j + 4], iB1);                         \
            oA0 = fmaf(w[3][j],     hsA[j],     oA0);                         \
            oB0 = fmaf(w[3][j],     hsB[j],     oB0);                         \
            oA1 = fmaf(w[3][j + 4], hsA[j + 4], oA1);                         \
            oB1 = fmaf(w[3][j + 4], hsB[j + 4], oB1);                         \
        }                                                                     \
        /* phase 3: all gate MUFUs, both chains */                            \
        const float vfA = tanha(fA0 + fA1);                                   \
        const float vfB = tanha(fB0 + fB1);                                   \
        const float vgA = tanha(gA0 + gA1);                                   \
        const float vgB = tanha(gB0 + gB1);                                   \
        const float viA = tanha(iA0 + iA1);                                   \
        const float viB = tanha(iB0 + iB1);                                   \
        const float voA = tanha(oA0 + oA1);                                   \
        const float voB = tanha(oB0 + oB1);                                   \
        /* phase 4: both c/h updates, interleaved */                          \
        const float fgA = fmaf(vfA, 0.5f, 0.5f);                              \
        const float fgB = fmaf(vfB, 0.5f, 0.5f);                              \
        const float igA = fmaf(viA, 0.5f, 0.5f);                              \
        const float igB = fmaf(viB, 0.5f, 0.5f);                              \
        const float ogA = fmaf(voA, 0.5f, 0.5f);                              \
        const float ogB = fmaf(voB, 0.5f, 0.5f);                              \
        cA = fmaf(fgA, cA, igA * vgA);                                        \
        cB = fmaf(fgB, cB, igB * vgB);                                        \
        const float thA = tanha(cA);                                          \
        const float thB = tanha(cB);                                          \
        hA = ogA * thA;                                                       \
        hB = ogB * thB;                                                       \
        ypA[(size_t)(T2) * 2048] = hA;                                        \
        ypB[(size_t)(T2) * 2048] = hB;                                        \
        if (DO_PF) {                                                          \
            bufA[k_] = __ldg(xpA + (size_t)((T2) + PF) * 2048);               \
            bufB[k_] = __ldg(xpB + (size_t)((T2) + PF) * 2048);               \
        }                                                                     \
    }

    int t = 0;
#pragma unroll 1
    for (; t < S_LEN - PF; t += PF) {
#pragma unroll
        for (int k = 0; k < PF; k++) K2_STEP2(t + k, true)
    }
#pragma unroll
    for (int k = 0; k < PF; k++) K2_STEP2(t + k, false)

    const size_t fb = (size_t)NROWS * OUTSZ;
    out[fb + blk * 64 + lane]      = hA;                          // h_f
    out[fb + blk * 64 + 32 + lane] = hB;
    out[fb + BATCH * HID + blk * 64 + lane]      = cA;            // c_f
    out[fb + BATCH * HID + blk * 64 + 32 + lane] = cB;
}

// ---------------------------------------------------------------------------
// K3: residual MLP head. Lane per (t,b) row through 80-block chain,
//     warp-transpose via shfl for the 128-wide expansion -> STG.128.
// ---------------------------------------------------------------------------
__global__ void __launch_bounds__(256) k3_res(
    const float* __restrict__ w_in,  const float* __restrict__ b_in,
    const float* __restrict__ rb_w1, const float* __restrict__ rb_b1,
    const float* __restrict__ rb_w2, const float* __restrict__ rb_b2,
    const float* __restrict__ w_bn,  const float* __restrict__ b_bn,
    const float* __restrict__ w_out, const float* __restrict__ b_out,
    float* __restrict__ out)
{
    __shared__ float4 s_w1[NBLK], s_w2[NBLK], s_b2[NBLK];
    __shared__ float  s_b1[NBLK];
    for (int i = threadIdx.x; i < NBLK; i += blockDim.x) {
        s_w1[i] = ((const float4*)rb_w1)[i];
        s_w2[i] = ((const float4*)rb_w2)[i];
        s_b2[i] = ((const float4*)rb_b2)[i];
        s_b1[i] = rb_b1[i];
    }
    __syncthreads();

    const int lane  = threadIdx.x & 31;
    const int warpg = (blockIdx.x * blockDim.x + threadIdx.x) >> 5;
    const int base  = warpg * 32;           // 16384 warps cover 524288 rows
    const int e     = base + lane;

    const float4 ha = *(const float4*)(g_ys + (size_t)e * 8);
    const float4 hb = *(const float4*)(g_ys + (size_t)e * 8 + 4);
    const float hv[8] = {ha.x, ha.y, ha.z, ha.w, hb.x, hb.y, hb.z, hb.w};

    float y[4];
#pragma unroll
    for (int i = 0; i < 4; i++) {
        float a = b_in[i];
#pragma unroll
        for (int j = 0; j < 8; j++) a = fmaf(w_in[i * 8 + j], hv[j], a);
        y[i] = leaky(a);
    }

#pragma unroll 2
    for (int blk = 0; blk < NBLK; blk++) {
        const float4 w1 = s_w1[blk];
        const float4 w2 = s_w2[blk];
        const float4 b2 = s_b2[blk];
        float z = s_b1[blk];
        z = fmaf(w1.x, y[0], z);
        z = fmaf(w1.y, y[1], z);
        z = fmaf(w1.z, y[2], z);
        z = fmaf(w1.w, y[3], z);
        z = leaky(z);
        y[0] = leaky(fmaf(w2.x, z, y[0]) + b2.x);
        y[1] = leaky(fmaf(w2.y, z, y[1]) + b2.y);
        y[2] = leaky(fmaf(w2.z, z, y[2]) + b2.z);
        y[3] = leaky(fmaf(w2.w, z, y[3]) + b2.w);
    }

    float yb = b_bn[0];
    yb = fmaf(w_bn[0], y[0], yb);
    yb = fmaf(w_bn[1], y[1], yb);
    yb = fmaf(w_bn[2], y[2], yb);
    yb = fmaf(w_bn[3], y[3], yb);
    yb = leaky(yb);

    // sigmoid(a*w+b) = 0.5 + 0.5*tanh(0.5*(a*w+b)) -> pre-halved w,b
    float4 wo = *(const float4*)(w_out + lane * 4);
    float4 bo = *(const float4*)(b_out + lane * 4);
    wo.x *= 0.5f; wo.y *= 0.5f; wo.z *= 0.5f; wo.w *= 0.5f;
    bo.x *= 0.5f; bo.y *= 0.5f; bo.z *= 0.5f; bo.w *= 0.5f;
    float* op = out + (size_t)base * OUTSZ + lane * 4;

#pragma unroll
    for (int cidx = 0; cidx < 32; cidx++) {
        const float ybc = __shfl_sync(0xffffffffu, yb, cidx);
        float4 o;
        o.x = fmaf(tanha(fmaf(ybc, wo.x, bo.x)), 0.5f, 0.5f);
        o.y = fmaf(tanha(fmaf(ybc, wo.y, bo.y)), 0.5f, 0.5f);
        o.z = fmaf(tanha(fmaf(ybc, wo.z, bo.z)), 0.5f, 0.5f);
        o.w = fmaf(tanha(fmaf(ybc, wo.w, bo.w)), 0.5f, 0.5f);
        *(float4*)(op + (size_t)cidx * OUTSZ) = o;
    }
}

// ---------------------------------------------------------------------------
extern "C" void kernel_launch(void* const* d_in, const int* in_sizes, int n_in,
                              void* d_out, int out_size)
{
    const float* x     = (const float*)d_in[0];
    const float* h     = (const float*)d_in[1];
    const float* c     = (const float*)d_in[2];
    const float* w_ih  = (const float*)d_in[3];
    const float* w_hh  = (const float*)d_in[4];
    const float* b_ih  = (const float*)d_in[5];
    const float* b_hh  = (const float*)d_in[6];
    const float* w_in  = (const float*)d_in[7];
    const float* b_in  = (const float*)d_in[8];
    const float* rb_w1 = (const float*)d_in[9];
    const float* rb_b1 = (const float*)d_in[10];
    const float* rb_w2 = (const float*)d_in[11];
    const float* rb_b2 = (const float*)d_in[12];
    const float* w_bn  = (const float*)d_in[13];
    const float* b_bn  = (const float*)d_in[14];
    const float* w_out = (const float*)d_in[15];
    const float* b_out = (const float*)d_in[16];
    float* out = (float*)d_out;

    k1_xw<<<2048, 256>>>(x, w_ih, b_ih, b_hh);
    k2_lstm<<<BATCH / 8, 32>>>(h, c, w_hh, out);
    k3_res<<<2048, 256>>>(w_in, b_in, rb_w1, rb_b1, rb_w2, rb_b2,
                          w_bn, b_bn, w_out, b_out, out);
}

// round 7
// speedup vs baseline: 1.4888x; 1.4836x over previous
#include <cuda_runtime.h>
#include <cstdint>

#define S_LEN 2048
#define BATCH 256
#define INSZ  32
#define HID   8
#define G4    32          // 4*HID gates
#define NBLK  80
#define OUTSZ 128
#define NROWS (S_LEN*BATCH)   // 524288

// Scratch (__device__ globals; no runtime allocation)
// g_xg layout: [row][unit*4 + gate_type]  (i,f,g,o interleaved per unit)
__device__ float g_xg[(size_t)NROWS * G4];   // 64 MB
__device__ float g_ys[(size_t)NROWS * HID];  // 16 MB: LSTM hidden outputs

__device__ __forceinline__ float tanha(float x) {
    float r; asm("tanh.approx.f32 %0, %1;" : "=f"(r) : "f"(x)); return r;
}
__device__ __forceinline__ float leaky(float v) { return fmaxf(v, 0.01f * v); }

// ---------------------------------------------------------------------------
// K1: xg[row][u*4+t] = s(t) * ( x[row].w_ih[t*8+u] + b_ih + b_hh )
//     s = 0.5 for sigmoid gates (i,f,o), 1.0 for tanh gate.
// ---------------------------------------------------------------------------
__global__ void __launch_bounds__(256) k1_xw(
    const float* __restrict__ x, const float* __restrict__ w_ih,
    const float* __restrict__ b_ih, const float* __restrict__ b_hh)
{
    __shared__ float4 sx[256 * 8];     // 32 KB: 256 rows of x
    __shared__ float  swp[32 * 33];    // padded weights

    const int tid  = threadIdx.x;
    const int lane = tid & 31;
    const int wid  = tid >> 5;

#pragma unroll
    for (int k = 0; k < 4; k++) {
        const int idx = tid + k * 256;          // 1024 floats
        const int g = idx >> 5, j = idx & 31;
        const float s = ((g >> 3) == 2) ? 1.f : 0.5f;
        swp[g * 33 + j] = w_ih[idx] * s;
    }

    const size_t rowbase = (size_t)blockIdx.x * 256;
    const float4* xg4 = (const float4*)x + rowbase * 8;
#pragma unroll
    for (int i = 0; i < 8; i++) sx[tid + i * 256] = xg4[tid + i * 256];

    __syncthreads();

    float w[32];
#pragma unroll
    for (int j = 0; j < 32; j++) w[j] = swp[lane * 33 + j];
    const float s2 = ((lane >> 3) == 2) ? 1.f : 0.5f;
    const float bias = (b_ih[lane] + b_hh[lane]) * s2;

    // unit-major output column: u*4 + type
    const int ocol = (lane & 7) * 4 + (lane >> 3);

    float* op = g_xg + (rowbase + wid * 32) * 32 + ocol;
    const float4* xr0 = &sx[wid * 32 * 8];

#pragma unroll 4
    for (int r = 0; r < 32; r++) {
        const float4* xr = xr0 + r * 8;
        float a0 = bias, a1 = 0.f, a2 = 0.f, a3 = 0.f;
#pragma unroll
        for (int j4 = 0; j4 < 8; j4++) {
            const float4 v = xr[j4];            // broadcast LDS.128
            a0 = fmaf(w[j4 * 4 + 0], v.x, a0);
            a1 = fmaf(w[j4 * 4 + 1], v.y, a1);
            a2 = fmaf(w[j4 * 4 + 2], v.z, a2);
            a3 = fmaf(w[j4 * 4 + 3], v.w, a3);
        }
        op[(size_t)r * 32] = (a0 + a1) + (a2 + a3);   // coalesced STG.32
    }
}

// ---------------------------------------------------------------------------
// K2: sequential LSTM. 4 batch chains per warp (lane = bsub*8+unit); each
//     lane computes all 4 gates of its unit. h-exchange via DOUBLE-BUFFERED
//     SHARED MEMORY (1 STS + 1 WARPSYNC + 2 broadcast LDS.128 per step)
//     instead of 8 SHFLs -- the shuffles' per-op MIO issue cost was the
//     measured per-warp throughput bound.
// ---------------------------------------------------------------------------
#define PF 8
__global__ void __launch_bounds__(32, 1) k2_lstm(
    const float* __restrict__ h0, const float* __restrict__ c0,
    const float* __restrict__ w_hh, float* __restrict__ out)
{
    __shared__ float sh[2][32];

    const int lane = threadIdx.x;
    const int blk  = blockIdx.x;           // 64 blocks, 4 batch elems each
    const int unit = lane & 7;
    const int bsub = lane >> 3;

    // weights: gate rows unit, unit+8, unit+16, unit+24; pre-scale 0.5 (i,f,o)
    float w[4][8];
#pragma unroll
    for (int t = 0; t < 4; t++) {
        const float s = (t == 2) ? 1.f : 0.5f;
#pragma unroll
        for (int j = 0; j < 8; j++) w[t][j] = w_hh[(t * 8 + unit) * 8 + j] * s;
    }

    float h = h0[blk * 32 + lane];   // [b][u] = blk*32 + bsub*8 + unit
    float c = c0[blk * 32 + lane];

    // xg float4 index: t*2048 + blk*32 + lane
    const float4* xp = (const float4*)g_xg + (size_t)blk * 32 + lane;
    float* yp = g_ys + blk * 32 + lane;                 // + t*2048

    float4 buf[PF];
#pragma unroll
    for (int k = 0; k < PF; k++) buf[k] = __ldg(xp + (size_t)k * 2048);

    sh[0][lane] = h;
    __syncwarp();

#define K2_STEP(T2, DO_PF)                                                    \
    {                                                                         \
        const int k_  = (T2) & (PF - 1);                                      \
        const int par = (T2) & 1;                                             \
        const float4 xg = buf[k_];                                            \
        /* read group's 8 h values: two broadcast LDS.128 */                  \
        const float4 hlo = *(const float4*)&sh[par][bsub * 8];                \
        const float4 hhi = *(const float4*)&sh[par][bsub * 8 + 4];            \
        float i0 = xg.x, f0 = xg.y, gg0 = xg.z, o0 = xg.w;                    \
        float i1 = 0.f, f1 = 0.f, gg1 = 0.f, o1 = 0.f;                        \
        f0  = fmaf(w[1][0], hlo.x, f0);                                       \
        f1  = fmaf(w[1][4], hhi.x, f1);                                       \
        gg0 = fmaf(w[2][0], hlo.x, gg0);                                      \
        gg1 = fmaf(w[2][4], hhi.x, gg1);                                      \
        i0  = fmaf(w[0][0], hlo.x, i0);                                       \
        i1  = fmaf(w[0][4], hhi.x, i1);                                       \
        o0  = fmaf(w[3][0], hlo.x, o0);                                       \
        o1  = fmaf(w[3][4], hhi.x, o1);                                       \
        f0  = fmaf(w[1][1], hlo.y, f0);                                       \
        f1  = fmaf(w[1][5], hhi.y, f1);                                       \
        gg0 = fmaf(w[2][1], hlo.y, gg0);                                      \
        gg1 = fmaf(w[2][5], hhi.y, gg1);                                      \
        i0  = fmaf(w[0][1], hlo.y, i0);                                       \
        i1  = fmaf(w[0][5], hhi.y, i1);                                       \
        o0  = fmaf(w[3][1], hlo.y, o0);                                       \
        o1  = fmaf(w[3][5], hhi.y, o1);                                       \
        f0  = fmaf(w[1][2], hlo.z, f0);                                       \
        f1  = fmaf(w[1][6], hhi.z, f1);                                       \
        gg0 = fmaf(w[2][2], hlo.z, gg0);                                      \
        gg1 = fmaf(w[2][6], hhi.z, gg1);                                      \
        i0  = fmaf(w[0][2], hlo.z, i0);                                       \
        i1  = fmaf(w[0][6], hhi.z, i1);                                       \
        o0  = fmaf(w[3][2], hlo.z, o0);                                       \
        o1  = fmaf(w[3][6], hhi.z, o1);                                       \
        f0  = fmaf(w[1][3], hlo.w, f0);                                       \
        f1  = fmaf(w[1][7], hhi.w, f1);                                       \
        gg0 = fmaf(w[2][3], hlo.w, gg0);                                      \
        gg1 = fmaf(w[2][7], hhi.w, gg1);                                      \
        i0  = fmaf(w[0][3], hlo.w, i0);                                       \
        i1  = fmaf(w[0][7], hhi.w, i1);                                       \
        o0  = fmaf(w[3][3], hlo.w, o0);                                       \
        o1  = fmaf(w[3][7], hhi.w, o1);                                       \
        const float vf = tanha(f0 + f1);                                      \
        const float vg = tanha(gg0 + gg1);                                    \
        const float vi = tanha(i0 + i1);                                      \
        const float vo = tanha(o0 + o1);                                      \
        const float fg = fmaf(vf, 0.5f, 0.5f);                                \
        const float ig = fmaf(vi, 0.5f, 0.5f);                                \
        const float og = fmaf(vo, 0.5f, 0.5f);                                \
        c = fmaf(fg, c, ig * vg);                                             \
        h = og * tanha(c);                                                    \
        sh[par ^ 1][lane] = h;                                                \
        yp[(size_t)(T2) * 2048] = h;                                          \
        if (DO_PF)                                                            \
            buf[k_] = __ldg(xp + (size_t)((T2) + PF) * 2048);                 \
        __syncwarp();                                                         \
    }

    int t = 0;
#pragma unroll 1
    for (; t < S_LEN - PF; t += PF) {
#pragma unroll
        for (int k = 0; k < PF; k++) K2_STEP(t + k, true)
    }
#pragma unroll
    for (int k = 0; k < PF; k++) K2_STEP(t + k, false)

    const size_t fb = (size_t)NROWS * OUTSZ;
    out[fb + blk * 32 + lane] = h;                          // h_f
    out[fb + BATCH * HID + blk * 32 + lane] = c;            // c_f
}

// ---------------------------------------------------------------------------
// K3: residual MLP head. Lane per (t,b) row through 80-block chain,
//     warp-transpose via shfl for the 128-wide expansion -> STG.128.
// ---------------------------------------------------------------------------
__global__ void __launch_bounds__(256) k3_res(
    const float* __restrict__ w_in,  const float* __restrict__ b_in,
    const float* __restrict__ rb_w1, const float* __restrict__ rb_b1,
    const float* __restrict__ rb_w2, const float* __restrict__ rb_b2,
    const float* __restrict__ w_bn,  const float* __restrict__ b_bn,
    const float* __restrict__ w_out, const float* __restrict__ b_out,
    float* __restrict__ out)
{
    __shared__ float4 s_w1[NBLK], s_w2[NBLK], s_b2[NBLK];
    __shared__ float  s_b1[NBLK];
    for (int i = threadIdx.x; i < NBLK; i += blockDim.x) {
        s_w1[i] = ((const float4*)rb_w1)[i];
        s_w2[i] = ((const float4*)rb_w2)[i];
        s_b2[i] = ((const float4*)rb_b2)[i];
        s_b1[i] = rb_b1[i];
    }
    __syncthreads();

    const int lane  = threadIdx.x & 31;
    const int warpg = (blockIdx.x * blockDim.x + threadIdx.x) >> 5;
    const int base  = warpg * 32;           // 16384 warps cover 524288 rows
    const int e     = base + lane;

    const float4 ha = *(const float4*)(g_ys + (size_t)e * 8);
    const float4 hb = *(const float4*)(g_ys + (size_t)e * 8 + 4);
    const float hv[8] = {ha.x, ha.y, ha.z, ha.w, hb.x, hb.y, hb.z, hb.w};

    float y[4];
#pragma unroll
    for (int i = 0; i < 4; i++) {
        float a = b_in[i];
#pragma unroll
        for (int j = 0; j < 8; j++) a = fmaf(w_in[i * 8 + j], hv[j], a);
        y[i] = leaky(a);
    }

#pragma unroll 2
    for (int blk = 0; blk < NBLK; blk++) {
        const float4 w1 = s_w1[blk];
        const float4 w2 = s_w2[blk];
        const float4 b2 = s_b2[blk];
        float z = s_b1[blk];
        z = fmaf(w1.x, y[0], z);
        z = fmaf(w1.y, y[1], z);
        z = fmaf(w1.z, y[2], z);
        z = fmaf(w1.w, y[3], z);
        z = leaky(z);
        y[0] = leaky(fmaf(w2.x, z, y[0]) + b2.x);
        y[1] = leaky(fmaf(w2.y, z, y[1]) + b2.y);
        y[2] = leaky(fmaf(w2.z, z, y[2]) + b2.z);
        y[3] = leaky(fmaf(w2.w, z, y[3]) + b2.w);
    }

    float yb = b_bn[0];
    yb = fmaf(w_bn[0], y[0], yb);
    yb = fmaf(w_bn[1], y[1], yb);
    yb = fmaf(w_bn[2], y[2], yb);
    yb = fmaf(w_bn[3], y[3], yb);
    yb = leaky(yb);

    // sigmoid(a*w+b) = 0.5 + 0.5*tanh(0.5*(a*w+b)) -> pre-halved w,b
    float4 wo = *(const float4*)(w_out + lane * 4);
    float4 bo = *(const float4*)(b_out + lane * 4);
    wo.x *= 0.5f; wo.y *= 0.5f; wo.z *= 0.5f; wo.w *= 0.5f;
    bo.x *= 0.5f; bo.y *= 0.5f; bo.z *= 0.5f; bo.w *= 0.5f;
    float* op = out + (size_t)base * OUTSZ + lane * 4;

#pragma unroll
    for (int cidx = 0; cidx < 32; cidx++) {
        const float ybc = __shfl_sync(0xffffffffu, yb, cidx);
        float4 o;
        o.x = fmaf(tanha(fmaf(ybc, wo.x, bo.x)), 0.5f, 0.5f);
        o.y = fmaf(tanha(fmaf(ybc, wo.y, bo.y)), 0.5f, 0.5f);
        o.z = fmaf(tanha(fmaf(ybc, wo.z, bo.z)), 0.5f, 0.5f);
        o.w = fmaf(tanha(fmaf(ybc, wo.w, bo.w)), 0.5f, 0.5f);
        *(float4*)(op + (size_t)cidx * OUTSZ) = o;
    }
}

// ---------------------------------------------------------------------------
extern "C" void kernel_launch(void* const* d_in, const int* in_sizes, int n_in,
                              void* d_out, int out_size)
{
    const float* x     = (const float*)d_in[0];
    const float* h     = (const float*)d_in[1];
    const float* c     = (const float*)d_in[2];
    const float* w_ih  = (const float*)d_in[3];
    const float* w_hh  = (const float*)d_in[4];
    const float* b_ih  = (const float*)d_in[5];
    const float* b_hh  = (const float*)d_in[6];
    const float* w_in  = (const float*)d_in[7];
    const float* b_in  = (const float*)d_in[8];
    const float* rb_w1 = (const float*)d_in[9];
    const float* rb_b1 = (const float*)d_in[10];
    const float* rb_w2 = (const float*)d_in[11];
    const float* rb_b2 = (const float*)d_in[12];
    const float* w_bn  = (const float*)d_in[13];
    const float* b_bn  = (const float*)d_in[14];
    const float* w_out = (const float*)d_in[15];
    const float* b_out = (const float*)d_in[16];
    float* out = (float*)d_out;

    k1_xw<<<2048, 256>>>(x, w_ih, b_ih, b_hh);
    k2_lstm<<<BATCH / 4, 32>>>(h, c, w_hh, out);
    k3_res<<<2048, 256>>>(w_in, b_in, rb_w1, rb_b1, rb_w2, rb_b2,
                          w_bn, b_bn, w_out, b_out, out);
}